// round 16
// baseline (speedup 1.0000x reference)
#include <cuda_runtime.h>
#include <cuda_fp16.h>
#include <cstdint>
#include <cstddef>

// ---------------------------------------------------------------------------
// Problem constants
// ---------------------------------------------------------------------------
constexpr int N_ATOMS  = 100000;
constexpr int N_BONDS  = 200001;
constexpr int ATOM_FDIM = 39;
constexpr int IN_FDIM   = 50;
constexpr int OUT_FDIM  = 295;
constexpr int MAX_NB    = 6;
constexpr int HIDDEN    = 256;
constexpr int N_MOLS    = 2000;
constexpr int APM       = 50;

constexpr int BK  = 128;   // eight m16n8k16 steps per chunk (2 barriers/round)
constexpr int BM  = 64;    // M tile
constexpr int THREADS = 512;   // 16 warps, 1 CTA/SM (smem-bound)

constexpr int KP0 = 128;   // init K (50 -> 128)
constexpr int KP1 = 256;   // rounds K
constexpr int KP2 = 384;   // readout K: [nei(256) | fatoms(39) | pad(89)]

// ---------------------------------------------------------------------------
// Scratch (fp16 everywhere except final pool output)
// ---------------------------------------------------------------------------
__device__ __align__(16) __half g_binput[(size_t)N_BONDS * HIDDEN];
__device__ __align__(16) __half g_msg0  [(size_t)N_BONDS * HIDDEN];
__device__ __align__(16) __half g_msg1  [(size_t)N_BONDS * HIDDEN];
__device__ __align__(16) __half g_atomh [(size_t)N_ATOMS * HIDDEN];
__device__ __align__(16) __half g_fbpad [(size_t)N_BONDS * KP0];
__device__ __align__(16) __half g_afeat [(size_t)N_ATOMS * 128];
__device__ __align__(16) __half g_Wi    [(size_t)HIDDEN * KP0];   // [n][k]
__device__ __align__(16) __half g_Wh    [(size_t)HIDDEN * KP1];   // [n][k]
__device__ __align__(16) __half g_Wo    [(size_t)HIDDEN * KP2];   // [n][k], cols reordered

// ---------------------------------------------------------------------------
// Helpers
// ---------------------------------------------------------------------------
__device__ __forceinline__ uint32_t smem_u32(const void* p) {
    uint32_t a;
    asm("{ .reg .u64 t; cvta.to.shared.u64 t, %1; cvt.u32.u64 %0, t; }" : "=r"(a) : "l"(p));
    return a;
}
__device__ __forceinline__ void cp16(uint32_t dst, const void* src, uint32_t sz) {
    asm volatile("cp.async.ca.shared.global [%0], [%1], 16, %2;" :: "r"(dst), "l"(src), "r"(sz) : "memory");
}
__device__ __forceinline__ void cp_commit() {
    asm volatile("cp.async.commit_group;" ::: "memory");
}
template <int N>
__device__ __forceinline__ void cp_wait() {
    asm volatile("cp.async.wait_group %0;" :: "n"(N) : "memory");
}
// fp16 inputs, fp32 accumulate
__device__ __forceinline__ void mma16(float& d0, float& d1, float& d2, float& d3,
                                      uint32_t a0, uint32_t a1, uint32_t a2, uint32_t a3,
                                      uint32_t b0, uint32_t b1) {
    asm volatile(
        "mma.sync.aligned.m16n8k16.row.col.f32.f16.f16.f32 "
        "{%0,%1,%2,%3}, {%4,%5,%6,%7}, {%8,%9}, {%0,%1,%2,%3};"
        : "+f"(d0), "+f"(d1), "+f"(d2), "+f"(d3)
        : "r"(a0), "r"(a1), "r"(a2), "r"(a3), "r"(b0), "r"(b1));
}

// SMEM layout (bytes), TWO-stage rings, BK=128 chunks,
// tile row stride 136 halfs (128 + 8 pad) = 272B (conflict-free frags).
constexpr int GOFF_B  = 0;                        // 64 rows x 6 ints = 1536
constexpr int AOFF_B  = 1536;
constexpr int A_BUF_B = BM * 136 * 2;             // 17408
constexpr int BOFF_B  = AOFF_B + 2 * A_BUF_B;     // 36352
constexpr int B_BUF_B = 256 * 136 * 2;            // 69632
constexpr int SMEM_BYTES = BOFF_B + 2 * B_BUF_B;  // 175616 (1 CTA/SM)

// ---------------------------------------------------------------------------
// Fused gather + fp16 HMMA GEMM. 512 threads, 16 warps as 2(M) x 8(N);
// warp tile 32x32; 1 CTA/SM. BK=128: 8 k-steps per barrier interval.
// R14 phase ordering: issue p0 pre-MMA | 8 k-steps | store p0, issue p1,
// store p1 (tail covered by intra-interval slack).
// MODE 0: C2h <- raw fp16, Ch <- relu fp16     (init; no gather)
// MODE 1: Ch <- relu(binput + raw) fp16        (rounds; all chunks gathered)
// MODE 2: Ch <- relu(raw + b_o[n]) fp16        (readout; chunks <2 gathered)
// ---------------------------------------------------------------------------
template <int MODE, int KT>
__global__ void __launch_bounds__(THREADS, 1)
gemm_fused(const __half* __restrict__ msg,
           const int* __restrict__ graph,
           const __half* __restrict__ Apad, int ldah,
           const __half* __restrict__ Bt, int ldbh,
           const void* __restrict__ extra,
           __half* __restrict__ Ch,
           __half* __restrict__ C2h, int M) {
    extern __shared__ char smc[];
    int* sgidx = (int*)(smc + GOFF_B);
    const uint32_t sbase = smem_u32(smc);
    const int tid  = threadIdx.x;
    const int wid  = tid >> 5;
    const int lane = tid & 31;
    const int mBase = blockIdx.x * BM;
    const int warpM = (wid >> 3) * 32;   // 0 or 32
    const int warpN = (wid & 7) * 32;    // 0..224

    constexpr int FEAT0 = (MODE == 2) ? 2 : 0;   // 256/128 = 2 gathered chunks
    auto gathered = [](int s) { return MODE == 1 || (MODE == 2 && s < 2); };

    const int grow = tid >> 3;   // 0..63 (gather row)
    const int gc   = tid & 7;    // 16B slot within 128B half-chunk

    if (MODE != 0) {
        for (int i = tid; i < BM * MAX_NB; i += THREADS) {
            int gi = mBase * MAX_NB + i;
            sgidx[i] = (gi < M * MAX_NB) ? graph[gi] : 0;
        }
        __syncthreads();
    }
    const char* msgc = (const char*)msg;

    // phase ph covers bytes [ph*128 + gc*16, +16) of the 256B chunk
    auto issue_phase = [&](int s, int ph, uint4* v) {
#pragma unroll
        for (int j = 0; j < 6; ++j) {
            uint32_t idx = (uint32_t)sgidx[grow * 6 + j];
            v[j] = __ldg((const uint4*)(msgc + (size_t)idx * (HIDDEN * 2)
                                        + s * (BK * 2) + ph * 128 + gc * 16));
        }
    };
    auto sum_store = [&](int s, int ph, const uint4* v) {
        float f[8];
#pragma unroll
        for (int t = 0; t < 8; ++t) f[t] = 0.0f;
#pragma unroll
        for (int j = 0; j < 6; ++j) {
            const __half2* h2 = (const __half2*)&v[j];
#pragma unroll
            for (int q = 0; q < 4; ++q) {
                float2 e = __half22float2(h2[q]);
                f[q * 2] += e.x; f[q * 2 + 1] += e.y;
            }
        }
        uint4 r;
        __half2* rh = (__half2*)&r;
#pragma unroll
        for (int q = 0; q < 4; ++q) rh[q] = __floats2half2_rn(f[q * 2], f[q * 2 + 1]);
        *(uint4*)(smc + AOFF_B + (s & 1) * A_BUF_B + grow * 272 + ph * 128 + gc * 16) = r;
    };
    auto cpA = [&](int s) {
#pragma unroll
        for (int i = 0; i < 2; ++i) {
            int e = tid + i * THREADS;
            int row = e >> 4, h = e & 15;    // 64 rows x 16 x 16B
            int gm = mBase + row;
            const void* src = Apad + (size_t)gm * ldah + (s - FEAT0) * BK + h * 8;
            uint32_t dst = sbase + AOFF_B + (s & 1) * A_BUF_B + (row * 136 + h * 8) * 2;
            cp16(dst, src, (gm < M) ? 16u : 0u);
        }
    };
    auto cpB = [&](int s) {
#pragma unroll
        for (int i = 0; i < 8; ++i) {
            int e = tid + i * THREADS;
            int row = e >> 4, h = e & 15;    // 256 rows x 16 x 16B
            const void* src = Bt + (size_t)row * ldbh + s * BK + h * 8;
            uint32_t dst = sbase + BOFF_B + (s & 1) * B_BUF_B + (row * 136 + h * 8) * 2;
            cp16(dst, src, 16u);
        }
    };

    // --- prologue: stage chunk 0 (both gather phases issued back-to-back) ---
    if (gathered(0)) {
        uint4 v0[6], v1[6];
        issue_phase(0, 0, v0);
        issue_phase(0, 1, v1);
        sum_store(0, 0, v0);
        sum_store(0, 1, v1);
    } else cpA(0);
    cpB(0); cp_commit();
    cp_wait<0>();
    __syncthreads();

    float acc[2][4][4];
#pragma unroll
    for (int a = 0; a < 2; ++a)
#pragma unroll
        for (int b = 0; b < 4; ++b)
#pragma unroll
            for (int c = 0; c < 4; ++c) acc[a][b][c] = 0.0f;

    uint4 vh[6];   // gather prefetch buffer (reused by both phases)

#pragma unroll 1
    for (int s = 0; s < KT; ++s) {
        // stage s+1: gather phase-0 loads + cp.async (into the OTHER buffer)
        if (s + 1 < KT) {
            if (gathered(s + 1)) issue_phase(s + 1, 0, vh);
            else cpA(s + 1);
            cpB(s + 1);
        }
        cp_commit();

        const __half* bA = (const __half*)(smc + AOFF_B + (s & 1) * A_BUF_B);
        const __half* bB = (const __half*)(smc + BOFF_B + (s & 1) * B_BUF_B);

#pragma unroll
        for (int ks = 0; ks < 8; ++ks) {
            const int k0 = ks * 16 + (lane & 3) * 2;
            uint32_t afr[2][4];
#pragma unroll
            for (int mt = 0; mt < 2; ++mt) {
                const int r0 = warpM + mt * 16 + (lane >> 2);
                const int r1 = r0 + 8;
                afr[mt][0] = *(const uint32_t*)&bA[r0 * 136 + k0];
                afr[mt][1] = *(const uint32_t*)&bA[r1 * 136 + k0];
                afr[mt][2] = *(const uint32_t*)&bA[r0 * 136 + k0 + 8];
                afr[mt][3] = *(const uint32_t*)&bA[r1 * 136 + k0 + 8];
            }
#pragma unroll
            for (int nt = 0; nt < 4; ++nt) {
                const int nn = warpN + nt * 8 + (lane >> 2);
                uint32_t b0 = *(const uint32_t*)&bB[nn * 136 + k0];
                uint32_t b1 = *(const uint32_t*)&bB[nn * 136 + k0 + 8];
#pragma unroll
                for (int mt = 0; mt < 2; ++mt)
                    mma16(acc[mt][nt][0], acc[mt][nt][1], acc[mt][nt][2], acc[mt][nt][3],
                          afr[mt][0], afr[mt][1], afr[mt][2], afr[mt][3], b0, b1);
            }
        }

        // finish staging s+1's gather: store p0, issue p1, store p1 (R14 order)
        if (s + 1 < KT && gathered(s + 1)) {
            sum_store(s + 1, 0, vh);
            issue_phase(s + 1, 1, vh);
            sum_store(s + 1, 1, vh);
        }
        cp_wait<0>();
        __syncthreads();
    }

    // --- epilogue ---
#pragma unroll
    for (int mt = 0; mt < 2; ++mt) {
#pragma unroll
        for (int rg = 0; rg < 2; ++rg) {
            const int r = mBase + warpM + mt * 16 + (lane >> 2) + rg * 8;
            if (r < M) {
#pragma unroll
                for (int nt = 0; nt < 4; ++nt) {
                    const int col = warpN + nt * 8 + (lane & 3) * 2;
                    const size_t off = (size_t)r * HIDDEN + col;
                    float v0 = acc[mt][nt][rg * 2 + 0];
                    float v1 = acc[mt][nt][rg * 2 + 1];
                    if (MODE == 1) {
                        float2 ef = __half22float2(*(const __half2*)((const __half*)extra + off));
                        v0 += ef.x; v1 += ef.y;
                    }
                    if (MODE == 2) {
                        const float* bo = (const float*)extra;
                        v0 += __ldg(bo + col);
                        v1 += __ldg(bo + col + 1);
                    }
                    if (MODE == 0)
                        *(__half2*)(C2h + off) = __floats2half2_rn(v0, v1);
                    v0 = fmaxf(v0, 0.0f); v1 = fmaxf(v1, 0.0f);
                    *(__half2*)(Ch + off) = __floats2half2_rn(v0, v1);
                }
            }
        }
    }
}

// ---------------------------------------------------------------------------
// Producers
// ---------------------------------------------------------------------------
__global__ void pad_fb_k(const float* __restrict__ in, __half* __restrict__ out) {
    size_t i = (size_t)blockIdx.x * blockDim.x + threadIdx.x;
    if (i >= (size_t)N_BONDS * KP0) return;
    int r = (int)(i / KP0), c = (int)(i % KP0);
    out[i] = (c < IN_FDIM) ? __float2half_rn(in[(size_t)r * IN_FDIM + c]) : __half(0.f);
}
__global__ void cv_wi_k(const float* __restrict__ W, __half* __restrict__ out) {
    int i = blockIdx.x * blockDim.x + threadIdx.x;
    if (i >= HIDDEN * KP0) return;
    int n = i / KP0, k = i % KP0;
    out[i] = (k < IN_FDIM) ? __float2half_rn(W[(size_t)n * IN_FDIM + k]) : __half(0.f);
}
__global__ void cv_wh_k(const float* __restrict__ W, __half* __restrict__ out) {
    int i = blockIdx.x * blockDim.x + threadIdx.x;
    if (i >= HIDDEN * KP1) return;
    out[i] = __float2half_rn(W[i]);
}
__global__ void cv_wo_k(const float* __restrict__ W, __half* __restrict__ out) {
    int i = blockIdx.x * blockDim.x + threadIdx.x;
    if (i >= HIDDEN * KP2) return;
    int n = i / KP2, k = i % KP2;
    float v = 0.0f;
    if (k < 256) v = W[(size_t)n * OUT_FDIM + ATOM_FDIM + k];
    else if (k < OUT_FDIM) v = W[(size_t)n * OUT_FDIM + (k - 256)];
    out[i] = __float2half_rn(v);
}
__global__ void pad_afeat_k(const float* __restrict__ fatoms, __half* __restrict__ afeat) {
    int i = blockIdx.x * blockDim.x + threadIdx.x;
    if (i >= N_ATOMS * 128) return;
    int r = i / 128, c = i % 128;
    afeat[i] = (c < ATOM_FDIM) ? __float2half_rn(fatoms[(size_t)r * ATOM_FDIM + c]) : __half(0.f);
}

__global__ void pool_k(const __half* __restrict__ atomh, float* __restrict__ out) {
    const int mol = blockIdx.x;
    const int n   = threadIdx.x;
    const __half* base = atomh + (size_t)mol * APM * HIDDEN;
    float s = 0.0f;
#pragma unroll
    for (int i = 0; i < APM; ++i) s += __half2float(base[(size_t)i * HIDDEN + n]);
    out[(size_t)mol * HIDDEN + n] = s * (1.0f / (float)APM);
}

// ---------------------------------------------------------------------------
extern "C" void kernel_launch(void* const* d_in, const int* in_sizes, int n_in,
                              void* d_out, int out_size) {
    const float* fatoms = (const float*)d_in[0];
    const float* fbonds = (const float*)d_in[1];
    const int*   agraph = (const int*)  d_in[2];
    const int*   bgraph = (const int*)  d_in[3];
    const float* W_i = (const float*)d_in[5];
    const float* W_h = (const float*)d_in[6];
    const float* W_o = (const float*)d_in[7];
    const float* b_o = (const float*)d_in[8];
    float* out = (float*)d_out;

    __half *binput, *msg0, *msg1, *atomh, *fbpad, *afeat, *Wi, *Wh, *Wo;
    cudaGetSymbolAddress((void**)&binput, g_binput);
    cudaGetSymbolAddress((void**)&msg0,   g_msg0);
    cudaGetSymbolAddress((void**)&msg1,   g_msg1);
    cudaGetSymbolAddress((void**)&atomh,  g_atomh);
    cudaGetSymbolAddress((void**)&fbpad,  g_fbpad);
    cudaGetSymbolAddress((void**)&afeat,  g_afeat);
    cudaGetSymbolAddress((void**)&Wi,     g_Wi);
    cudaGetSymbolAddress((void**)&Wh,     g_Wh);
    cudaGetSymbolAddress((void**)&Wo,     g_Wo);

    cudaFuncSetAttribute(gemm_fused<0, KP0 / BK>, cudaFuncAttributeMaxDynamicSharedMemorySize, SMEM_BYTES);
    cudaFuncSetAttribute(gemm_fused<1, KP1 / BK>, cudaFuncAttributeMaxDynamicSharedMemorySize, SMEM_BYTES);
    cudaFuncSetAttribute(gemm_fused<2, KP2 / BK>, cudaFuncAttributeMaxDynamicSharedMemorySize, SMEM_BYTES);

    {
        size_t n = (size_t)N_BONDS * KP0;
        pad_fb_k<<<(unsigned)((n + 255) / 256), 256>>>(fbonds, fbpad);
        cv_wi_k<<<(HIDDEN * KP0 + 255) / 256, 256>>>(W_i, Wi);
        cv_wh_k<<<(HIDDEN * KP1 + 255) / 256, 256>>>(W_h, Wh);
        cv_wo_k<<<(HIDDEN * KP2 + 255) / 256, 256>>>(W_o, Wo);
        pad_afeat_k<<<(N_ATOMS * 128 + 255) / 256, 256>>>(fatoms, afeat);
    }

    const int tilesB = (N_BONDS + BM - 1) / BM;
    const int tilesA = (N_ATOMS + BM - 1) / BM;

    // init: binput(raw fp16) + msg0 = relu fp16 (KT=1)
    gemm_fused<0, KP0 / BK><<<tilesB, THREADS, SMEM_BYTES>>>(
        nullptr, nullptr, fbpad, KP0, Wi, KP0,
        nullptr, msg0, binput, N_BONDS);

    // 5 message-passing rounds (gather fused, KT=2 -> 2 barriers/round)
    __half* cur = msg0;
    __half* nxt = msg1;
    for (int r = 0; r < 5; ++r) {
        gemm_fused<1, KP1 / BK><<<tilesB, THREADS, SMEM_BYTES>>>(
            cur, bgraph, nullptr, 0, Wh, KP1,
            binput, nxt, nullptr, N_BONDS);
        __half* t = cur; cur = nxt; nxt = t;
    }

    // atom readout (fp16 out, KT=3: 2 gathered + 1 feature chunk)
    gemm_fused<2, KP2 / BK><<<tilesA, THREADS, SMEM_BYTES>>>(
        cur, agraph, afeat, 128, Wo, KP2,
        b_o, atomh, nullptr, N_ATOMS);

    // mean pool (fp32 accumulate)
    pool_k<<<N_MOLS, 256>>>(atomh, out);
}

// round 17
// speedup vs baseline: 1.1917x; 1.1917x over previous
#include <cuda_runtime.h>
#include <cuda_fp16.h>
#include <cstdint>
#include <cstddef>

// ---------------------------------------------------------------------------
// Problem constants
// ---------------------------------------------------------------------------
constexpr int N_ATOMS  = 100000;
constexpr int N_BONDS  = 200001;
constexpr int ATOM_FDIM = 39;
constexpr int IN_FDIM   = 50;
constexpr int OUT_FDIM  = 295;
constexpr int MAX_NB    = 6;
constexpr int HIDDEN    = 256;
constexpr int N_MOLS    = 2000;
constexpr int APM       = 50;

constexpr int BK  = 64;    // four m16n8k16 steps per chunk (R14 optimum)
constexpr int BM  = 64;    // M tile (256 threads, 2 CTAs/SM)

constexpr int KP0 = 64;    // init K (50 -> 64)
constexpr int KPR = 320;   // rounds K: [fbonds(64) | nei(256)]  (binput fused!)
constexpr int KP2 = 320;   // readout K: [nei(256) | fatoms(39) | pad]

// ---------------------------------------------------------------------------
// Scratch (fp16; g_binput ELIMINATED by the Wcat fusion)
// ---------------------------------------------------------------------------
__device__ __align__(16) __half g_msg0 [(size_t)N_BONDS * HIDDEN];
__device__ __align__(16) __half g_msg1 [(size_t)N_BONDS * HIDDEN];
__device__ __align__(16) __half g_atomh[(size_t)N_ATOMS * HIDDEN];
__device__ __align__(16) __half g_fbpad[(size_t)N_BONDS * KP0];
__device__ __align__(16) __half g_afeat[(size_t)N_ATOMS * 64];
__device__ __align__(16) __half g_Wi   [(size_t)HIDDEN * KP0];   // [n][k]
__device__ __align__(16) __half g_Wcat [(size_t)HIDDEN * KPR];   // [n][Wi(64)|Wh(256)]
__device__ __align__(16) __half g_Wo   [(size_t)HIDDEN * KP2];   // [n][k], cols reordered

// ---------------------------------------------------------------------------
// Helpers
// ---------------------------------------------------------------------------
__device__ __forceinline__ uint32_t smem_u32(const void* p) {
    uint32_t a;
    asm("{ .reg .u64 t; cvta.to.shared.u64 t, %1; cvt.u32.u64 %0, t; }" : "=r"(a) : "l"(p));
    return a;
}
__device__ __forceinline__ void cp16(uint32_t dst, const void* src, uint32_t sz) {
    asm volatile("cp.async.ca.shared.global [%0], [%1], 16, %2;" :: "r"(dst), "l"(src), "r"(sz) : "memory");
}
__device__ __forceinline__ void cp_commit() {
    asm volatile("cp.async.commit_group;" ::: "memory");
}
template <int N>
__device__ __forceinline__ void cp_wait() {
    asm volatile("cp.async.wait_group %0;" :: "n"(N) : "memory");
}
// fp16 inputs, fp32 accumulate
__device__ __forceinline__ void mma16(float& d0, float& d1, float& d2, float& d3,
                                      uint32_t a0, uint32_t a1, uint32_t a2, uint32_t a3,
                                      uint32_t b0, uint32_t b1) {
    asm volatile(
        "mma.sync.aligned.m16n8k16.row.col.f32.f16.f16.f32 "
        "{%0,%1,%2,%3}, {%4,%5,%6,%7}, {%8,%9}, {%0,%1,%2,%3};"
        : "+f"(d0), "+f"(d1), "+f"(d2), "+f"(d3)
        : "r"(a0), "r"(a1), "r"(a2), "r"(a3), "r"(b0), "r"(b1));
}

// SMEM layout (bytes), TWO-stage rings, BK=64 chunks, row stride 72 halfs.
constexpr int GOFF_B  = 0;                        // 64 rows x 6 ints = 1536
constexpr int AOFF_B  = 1536;
constexpr int A_BUF_B = BM * 72 * 2;              // 9216
constexpr int BOFF_B  = AOFF_B + 2 * A_BUF_B;     // 19968
constexpr int B_BUF_B = 256 * 72 * 2;             // 36864
constexpr int SMEM_BYTES = BOFF_B + 2 * B_BUF_B;  // 93696 (2 CTAs/SM)

// ---------------------------------------------------------------------------
// Fused gather + fp16 HMMA GEMM (R14 schedule).
// MODE 0: init    A = fbpad[64],                    C <- relu        (KT=1)
// MODE 1: rounds  A = [fbpad(ch 0) | nei(ch 1..4)], C <- relu        (KT=5)
//                 (binput folded into the GEMM via Wcat = [Wi|Wh])
// MODE 2: readout A = [nei(ch 0..3) | afeat(ch 4)], C <- relu(+b_o)  (KT=5)
// ---------------------------------------------------------------------------
template <int MODE, int KT>
__global__ void __launch_bounds__(256, 2)
gemm_fused(const __half* __restrict__ msg,
           const int* __restrict__ graph,
           const __half* __restrict__ Apad, int ldah,
           const __half* __restrict__ Bt, int ldbh,
           const float* __restrict__ bias,
           __half* __restrict__ Ch, int M) {
    extern __shared__ char smc[];
    int* sgidx = (int*)(smc + GOFF_B);
    const uint32_t sbase = smem_u32(smc);
    const int tid  = threadIdx.x;
    const int wid  = tid >> 5;
    const int lane = tid & 31;
    const int mBase = blockIdx.x * BM;
    const int warpM = (wid >> 2) * 32;   // 0 or 32
    const int warpN = (wid & 3) * 64;    // 0,64,128,192

    // gathered-chunk predicate + offsets
    //   MODE 1: chunk 0 = feature (fbpad), chunks 1..4 gathered (k off = s-1)
    //   MODE 2: chunks 0..3 gathered (k off = s), chunk 4 = feature (afeat)
    constexpr int GOFST = (MODE == 1) ? 1 : 0;          // gather k-chunk offset
    constexpr int FEAT0 = (MODE == 2) ? 4 : 0;          // feature-chunk base
    auto gathered = [](int s) {
        return (MODE == 1 && s >= 1) || (MODE == 2 && s < 4);
    };

    const int grow = tid >> 2;   // 0..63 (gather row)
    const int gc   = tid & 3;    // 16B slot within 64B half-chunk

    if (MODE != 0) {
        for (int i = tid; i < BM * MAX_NB; i += 256) {
            int gi = mBase * MAX_NB + i;
            sgidx[i] = (gi < M * MAX_NB) ? graph[gi] : 0;
        }
        __syncthreads();
    }
    const char* msgc = (const char*)msg;

    auto issue_phase = [&](int s, int ph, uint4* v) {
#pragma unroll
        for (int j = 0; j < 6; ++j) {
            uint32_t idx = (uint32_t)sgidx[grow * 6 + j];
            v[j] = __ldg((const uint4*)(msgc + (size_t)idx * (HIDDEN * 2)
                                        + (s - GOFST) * (BK * 2) + ph * 64 + gc * 16));
        }
    };
    auto sum_store = [&](int s, int ph, const uint4* v) {
        float f[8];
#pragma unroll
        for (int t = 0; t < 8; ++t) f[t] = 0.0f;
#pragma unroll
        for (int j = 0; j < 6; ++j) {
            const __half2* h2 = (const __half2*)&v[j];
#pragma unroll
            for (int q = 0; q < 4; ++q) {
                float2 e = __half22float2(h2[q]);
                f[q * 2] += e.x; f[q * 2 + 1] += e.y;
            }
        }
        uint4 r;
        __half2* rh = (__half2*)&r;
#pragma unroll
        for (int q = 0; q < 4; ++q) rh[q] = __floats2half2_rn(f[q * 2], f[q * 2 + 1]);
        *(uint4*)(smc + AOFF_B + (s & 1) * A_BUF_B + grow * 144 + ph * 64 + gc * 16) = r;
    };
    auto cpA = [&](int s) {
#pragma unroll
        for (int i = 0; i < 2; ++i) {
            int e = tid + i * 256;
            int row = e >> 3, h = e & 7;    // 64 rows x 8 x 16B
            int gm = mBase + row;
            const void* src = Apad + (size_t)gm * ldah + (s - FEAT0) * BK + h * 8;
            uint32_t dst = sbase + AOFF_B + (s & 1) * A_BUF_B + (row * 72 + h * 8) * 2;
            cp16(dst, src, (gm < M) ? 16u : 0u);
        }
    };
    auto cpB = [&](int s) {
#pragma unroll
        for (int i = 0; i < 8; ++i) {
            int e = tid + i * 256;
            int row = e >> 3, h = e & 7;    // 256 rows x 8 x 16B
            const void* src = Bt + (size_t)row * ldbh + s * BK + h * 8;
            uint32_t dst = sbase + BOFF_B + (s & 1) * B_BUF_B + (row * 72 + h * 8) * 2;
            cp16(dst, src, 16u);
        }
    };

    // --- prologue: stage chunk 0 ---
    if (gathered(0)) {
        uint4 v[6];
        issue_phase(0, 0, v); sum_store(0, 0, v);
        issue_phase(0, 1, v); sum_store(0, 1, v);
    } else cpA(0);
    cpB(0); cp_commit();
    cp_wait<0>();
    __syncthreads();

    float acc[2][8][4];
#pragma unroll
    for (int a = 0; a < 2; ++a)
#pragma unroll
        for (int b = 0; b < 8; ++b)
#pragma unroll
            for (int c = 0; c < 4; ++c) acc[a][b][c] = 0.0f;

    uint4 vh[6];   // gather prefetch buffer (reused by both phases)

#pragma unroll 1
    for (int s = 0; s < KT; ++s) {
        // stage s+1: gather phase-0 loads + cp.async (into the OTHER buffer)
        if (s + 1 < KT) {
            if (gathered(s + 1)) issue_phase(s + 1, 0, vh);
            else cpA(s + 1);
            cpB(s + 1);
        }
        cp_commit();

        const __half* bA = (const __half*)(smc + AOFF_B + (s & 1) * A_BUF_B);
        const __half* bB = (const __half*)(smc + BOFF_B + (s & 1) * B_BUF_B);

#pragma unroll
        for (int ks = 0; ks < 4; ++ks) {
            const int k0 = ks * 16 + (lane & 3) * 2;
            uint32_t afr[2][4];
#pragma unroll
            for (int mt = 0; mt < 2; ++mt) {
                const int r0 = warpM + mt * 16 + (lane >> 2);
                const int r1 = r0 + 8;
                afr[mt][0] = *(const uint32_t*)&bA[r0 * 72 + k0];
                afr[mt][1] = *(const uint32_t*)&bA[r1 * 72 + k0];
                afr[mt][2] = *(const uint32_t*)&bA[r0 * 72 + k0 + 8];
                afr[mt][3] = *(const uint32_t*)&bA[r1 * 72 + k0 + 8];
            }
#pragma unroll
            for (int nt = 0; nt < 8; ++nt) {
                const int nn = warpN + nt * 8 + (lane >> 2);
                uint32_t b0 = *(const uint32_t*)&bB[nn * 72 + k0];
                uint32_t b1 = *(const uint32_t*)&bB[nn * 72 + k0 + 8];
#pragma unroll
                for (int mt = 0; mt < 2; ++mt)
                    mma16(acc[mt][nt][0], acc[mt][nt][1], acc[mt][nt][2], acc[mt][nt][3],
                          afr[mt][0], afr[mt][1], afr[mt][2], afr[mt][3], b0, b1);
            }
        }

        // finish staging s+1's gather: store p0, issue p1, store p1 (R14 order)
        if (s + 1 < KT && gathered(s + 1)) {
            sum_store(s + 1, 0, vh);
            issue_phase(s + 1, 1, vh);
            sum_store(s + 1, 1, vh);
        }
        cp_wait<0>();
        __syncthreads();
    }

    // --- epilogue: relu (+ bias in MODE 2) ---
#pragma unroll
    for (int mt = 0; mt < 2; ++mt) {
#pragma unroll
        for (int rg = 0; rg < 2; ++rg) {
            const int r = mBase + warpM + mt * 16 + (lane >> 2) + rg * 8;
            if (r < M) {
#pragma unroll
                for (int nt = 0; nt < 8; ++nt) {
                    const int col = warpN + nt * 8 + (lane & 3) * 2;
                    const size_t off = (size_t)r * HIDDEN + col;
                    float v0 = acc[mt][nt][rg * 2 + 0];
                    float v1 = acc[mt][nt][rg * 2 + 1];
                    if (MODE == 2) {
                        v0 += __ldg(bias + col);
                        v1 += __ldg(bias + col + 1);
                    }
                    v0 = fmaxf(v0, 0.0f); v1 = fmaxf(v1, 0.0f);
                    *(__half2*)(Ch + off) = __floats2half2_rn(v0, v1);
                }
            }
        }
    }
}

// ---------------------------------------------------------------------------
// Producers
// ---------------------------------------------------------------------------
__global__ void pad_fb_k(const float* __restrict__ in, __half* __restrict__ out) {
    size_t i = (size_t)blockIdx.x * blockDim.x + threadIdx.x;
    if (i >= (size_t)N_BONDS * KP0) return;
    int r = (int)(i / KP0), c = (int)(i % KP0);
    out[i] = (c < IN_FDIM) ? __float2half_rn(in[(size_t)r * IN_FDIM + c]) : __half(0.f);
}
__global__ void cv_wi_k(const float* __restrict__ W, __half* __restrict__ out) {
    int i = blockIdx.x * blockDim.x + threadIdx.x;
    if (i >= HIDDEN * KP0) return;
    int n = i / KP0, k = i % KP0;
    out[i] = (k < IN_FDIM) ? __float2half_rn(W[(size_t)n * IN_FDIM + k]) : __half(0.f);
}
// Wcat[n][320] = [Wi[n][0..49] pad to 64 | Wh[n][0..255]]
__global__ void cv_wcat_k(const float* __restrict__ Wi, const float* __restrict__ Wh,
                          __half* __restrict__ out) {
    int i = blockIdx.x * blockDim.x + threadIdx.x;
    if (i >= HIDDEN * KPR) return;
    int n = i / KPR, k = i % KPR;
    float v = 0.0f;
    if (k < KP0) { if (k < IN_FDIM) v = Wi[(size_t)n * IN_FDIM + k]; }
    else v = Wh[(size_t)n * HIDDEN + (k - KP0)];
    out[i] = __float2half_rn(v);
}
__global__ void cv_wo_k(const float* __restrict__ W, __half* __restrict__ out) {
    int i = blockIdx.x * blockDim.x + threadIdx.x;
    if (i >= HIDDEN * KP2) return;
    int n = i / KP2, k = i % KP2;
    float v = 0.0f;
    if (k < 256) v = W[(size_t)n * OUT_FDIM + ATOM_FDIM + k];
    else if (k < OUT_FDIM) v = W[(size_t)n * OUT_FDIM + (k - 256)];
    out[i] = __float2half_rn(v);
}
__global__ void pad_afeat_k(const float* __restrict__ fatoms, __half* __restrict__ afeat) {
    int i = blockIdx.x * blockDim.x + threadIdx.x;
    if (i >= N_ATOMS * 64) return;
    int r = i / 64, c = i % 64;
    afeat[i] = (c < ATOM_FDIM) ? __float2half_rn(fatoms[(size_t)r * ATOM_FDIM + c]) : __half(0.f);
}

__global__ void pool_k(const __half* __restrict__ atomh, float* __restrict__ out) {
    const int mol = blockIdx.x;
    const int n   = threadIdx.x;
    const __half* base = atomh + (size_t)mol * APM * HIDDEN;
    float s = 0.0f;
#pragma unroll
    for (int i = 0; i < APM; ++i) s += __half2float(base[(size_t)i * HIDDEN + n]);
    out[(size_t)mol * HIDDEN + n] = s * (1.0f / (float)APM);
}

// ---------------------------------------------------------------------------
extern "C" void kernel_launch(void* const* d_in, const int* in_sizes, int n_in,
                              void* d_out, int out_size) {
    const float* fatoms = (const float*)d_in[0];
    const float* fbonds = (const float*)d_in[1];
    const int*   agraph = (const int*)  d_in[2];
    const int*   bgraph = (const int*)  d_in[3];
    const float* W_i = (const float*)d_in[5];
    const float* W_h = (const float*)d_in[6];
    const float* W_o = (const float*)d_in[7];
    const float* b_o = (const float*)d_in[8];
    float* out = (float*)d_out;

    __half *msg0, *msg1, *atomh, *fbpad, *afeat, *Wi, *Wcat, *Wo;
    cudaGetSymbolAddress((void**)&msg0,  g_msg0);
    cudaGetSymbolAddress((void**)&msg1,  g_msg1);
    cudaGetSymbolAddress((void**)&atomh, g_atomh);
    cudaGetSymbolAddress((void**)&fbpad, g_fbpad);
    cudaGetSymbolAddress((void**)&afeat, g_afeat);
    cudaGetSymbolAddress((void**)&Wi,    g_Wi);
    cudaGetSymbolAddress((void**)&Wcat,  g_Wcat);
    cudaGetSymbolAddress((void**)&Wo,    g_Wo);

    cudaFuncSetAttribute(gemm_fused<0, KP0 / BK>, cudaFuncAttributeMaxDynamicSharedMemorySize, SMEM_BYTES);
    cudaFuncSetAttribute(gemm_fused<1, KPR / BK>, cudaFuncAttributeMaxDynamicSharedMemorySize, SMEM_BYTES);
    cudaFuncSetAttribute(gemm_fused<2, KP2 / BK>, cudaFuncAttributeMaxDynamicSharedMemorySize, SMEM_BYTES);

    {
        size_t n = (size_t)N_BONDS * KP0;
        pad_fb_k<<<(unsigned)((n + 255) / 256), 256>>>(fbonds, fbpad);
        cv_wi_k<<<(HIDDEN * KP0 + 255) / 256, 256>>>(W_i, Wi);
        cv_wcat_k<<<(HIDDEN * KPR + 255) / 256, 256>>>(W_i, W_h, Wcat);
        cv_wo_k<<<(HIDDEN * KP2 + 255) / 256, 256>>>(W_o, Wo);
        pad_afeat_k<<<(N_ATOMS * 64 + 255) / 256, 256>>>(fatoms, afeat);
    }

    const int tilesB = (N_BONDS + BM - 1) / BM;
    const int tilesA = (N_ATOMS + BM - 1) / BM;

    // init: msg0 = relu(fbonds @ Wi^T)  (KT=1; binput never materialized)
    gemm_fused<0, KP0 / BK><<<tilesB, 256, SMEM_BYTES>>>(
        nullptr, nullptr, fbpad, KP0, Wi, KP0, nullptr, msg0, N_BONDS);

    // 5 rounds: nxt = relu([fbpad | gather(msg)] @ Wcat^T)  (KT=5)
    __half* cur = msg0;
    __half* nxt = msg1;
    for (int r = 0; r < 5; ++r) {
        gemm_fused<1, KPR / BK><<<tilesB, 256, SMEM_BYTES>>>(
            cur, bgraph, fbpad, KP0, Wcat, KPR, nullptr, nxt, N_BONDS);
        __half* t = cur; cur = nxt; nxt = t;
    }

    // readout: atomh = relu([gather(msg) | afeat] @ Wo^T + b_o)  (KT=5)
    gemm_fused<2, KP2 / BK><<<tilesA, 256, SMEM_BYTES>>>(
        cur, agraph, afeat, 64, Wo, KP2, b_o, atomh, N_ATOMS);

    // mean pool (fp32 accumulate)
    pool_k<<<N_MOLS, 256>>>(atomh, out);
}